// round 1
// baseline (speedup 1.0000x reference)
#include <cuda_runtime.h>

#define B_   64
#define T_   2048
#define H_   512
#define E_   256
#define V_   50000
#define G4H_ 2048

// ---------------- scratch (allocation-free: device globals) ----------------
__device__ float g_embg[B_ * E_];     // gathered embeddings        (B,E)
__device__ float g_dec[B_ * H_];      // h @ W_dec^T                (B,H)
__device__ float g_scores[B_ * T_];   // attention scores pre-softmax
__device__ float g_ctx[B_ * H_];      // context                    (B,H)
__device__ float g_gates[B_ * G4H_];  // LSTM gates                 (B,4H)

// ---------------- fast-but-accurate transcendentals ----------------
__device__ __forceinline__ float tanh_fast(float x) {
    // tanh(x) = 1 - 2/(e^{2x}+1); EX2+RCP, abs err ~1e-7, handles +-inf limits
    float e = __expf(2.f * x);
    return 1.f - __fdividef(2.f, e + 1.f);
}
__device__ __forceinline__ float sig_fast(float x) {
    return __fdividef(1.f, 1.f + __expf(-x));
}

// ---------------- tiny kernels ----------------
__global__ void k_embed(const int* __restrict__ tok, const float* __restrict__ emb) {
    int b = blockIdx.x;
    g_embg[b * E_ + threadIdx.x] = emb[tok[b] * E_ + threadIdx.x];
}

// dec[b][h] = sum_k hidden[b][k] * W_dec[h][k]
__global__ void k_dec(const float* __restrict__ hidden, const float* __restrict__ Wdec) {
    int b = blockIdx.x;
    __shared__ float sh[H_];
    int tid = threadIdx.x;
    for (int i = tid; i < H_; i += 256) sh[i] = hidden[b * H_ + i];
    __syncthreads();
    int w = tid >> 5, lane = tid & 31;
    for (int h = w; h < H_; h += 8) {
        float acc = 0.f;
        for (int k = lane; k < H_; k += 32) acc += sh[k] * Wdec[h * H_ + k];
        #pragma unroll
        for (int o = 16; o; o >>= 1) acc += __shfl_down_sync(0xffffffffu, acc, o);
        if (!lane) g_dec[b * H_ + h] = acc;
    }
}

// ---------------- fused energy GEMM + tanh + v-dot -> scores ----------------
// scores[b,t] = sum_h v[h] * tanh( sum_k enc[b,t,k]*W_enc[h,k] + dec[b,h] )
// 64-row tiles (32 blocks per b, never straddles batch), 64-col chunks, K chunks of 64.
__global__ __launch_bounds__(256) void k_energy(
    const float* __restrict__ enc, const float* __restrict__ Wenc,
    const float* __restrict__ vat)
{
    __shared__ __align__(16) float A_s[64][68];  // [k][row]
    __shared__ __align__(16) float B_s[64][68];  // [k][col]
    __shared__ float dv[H_];
    __shared__ float vv[H_];
    __shared__ float red[64][17];

    int tid = threadIdx.x;
    int tx = tid & 15, ty = tid >> 4;
    int m0 = blockIdx.x * 64;
    int b  = m0 >> 11;                     // m0 / 2048

    for (int i = tid; i < H_; i += 256) { dv[i] = g_dec[b * H_ + i]; vv[i] = vat[i]; }

    float spart[4] = {0.f, 0.f, 0.f, 0.f};

    for (int c0 = 0; c0 < H_; c0 += 64) {
        float acc[4][4];
        #pragma unroll
        for (int i = 0; i < 4; i++)
            #pragma unroll
            for (int j = 0; j < 4; j++) acc[i][j] = 0.f;

        for (int k0 = 0; k0 < H_; k0 += 64) {
            __syncthreads();
            #pragma unroll
            for (int idx = tid; idx < 4096; idx += 256) {
                int r = idx >> 6, k = idx & 63;
                A_s[k][r] = enc[(m0 + r) * H_ + k0 + k];
                B_s[k][r] = Wenc[(c0 + r) * H_ + k0 + k];
            }
            __syncthreads();
            #pragma unroll
            for (int k = 0; k < 64; k++) {
                float4 a = *(const float4*)(&A_s[k][ty * 4]);
                float4 w = *(const float4*)(&B_s[k][tx * 4]);
                acc[0][0] += a.x * w.x; acc[0][1] += a.x * w.y; acc[0][2] += a.x * w.z; acc[0][3] += a.x * w.w;
                acc[1][0] += a.y * w.x; acc[1][1] += a.y * w.y; acc[1][2] += a.y * w.z; acc[1][3] += a.y * w.w;
                acc[2][0] += a.z * w.x; acc[2][1] += a.z * w.y; acc[2][2] += a.z * w.z; acc[2][3] += a.z * w.w;
                acc[3][0] += a.w * w.x; acc[3][1] += a.w * w.y; acc[3][2] += a.w * w.z; acc[3][3] += a.w * w.w;
            }
        }
        // fused epilogue: tanh + weighted reduce over this column chunk
        #pragma unroll
        for (int i = 0; i < 4; i++) {
            #pragma unroll
            for (int j = 0; j < 4; j++) {
                int col = c0 + tx * 4 + j;
                float e = tanh_fast(acc[i][j] + dv[col]);
                spart[i] += e * vv[col];
            }
        }
    }
    __syncthreads();
    #pragma unroll
    for (int i = 0; i < 4; i++) red[ty * 4 + i][tx] = spart[i];
    __syncthreads();
    if (tid < 64) {
        float s = 0.f;
        #pragma unroll
        for (int j = 0; j < 16; j++) s += red[tid][j];
        g_scores[m0 + tid] = s;
    }
}

// ---------------- softmax over T per batch row ----------------
__global__ void k_softmax(float* __restrict__ attn) {
    int b = blockIdx.x;
    int tid = threadIdx.x;  // 256
    __shared__ float se[T_];
    __shared__ float rbuf[10];

    float m = -1e30f;
    for (int i = tid; i < T_; i += 256) { float v = g_scores[b * T_ + i]; se[i] = v; m = fmaxf(m, v); }
    #pragma unroll
    for (int o = 16; o; o >>= 1) m = fmaxf(m, __shfl_xor_sync(0xffffffffu, m, o));
    if ((tid & 31) == 0) rbuf[tid >> 5] = m;
    __syncthreads();
    if (tid == 0) { float v = rbuf[0]; for (int i = 1; i < 8; i++) v = fmaxf(v, rbuf[i]); rbuf[8] = v; }
    __syncthreads();
    m = rbuf[8];

    float s = 0.f;
    for (int i = tid; i < T_; i += 256) { float e = __expf(se[i] - m); se[i] = e; s += e; }
    #pragma unroll
    for (int o = 16; o; o >>= 1) s += __shfl_xor_sync(0xffffffffu, s, o);
    if ((tid & 31) == 0) rbuf[tid >> 5] = s;
    __syncthreads();
    if (tid == 0) { float v = 0.f; for (int i = 0; i < 8; i++) v += rbuf[i]; rbuf[9] = v; }
    __syncthreads();
    float inv = __fdividef(1.f, rbuf[9]);
    for (int i = tid; i < T_; i += 256) attn[b * T_ + i] = se[i] * inv;
}

// ---------------- context[b,h] = sum_t attn[b,t] * enc[b,t,h] ----------------
__global__ void k_context(const float* __restrict__ attn, const float* __restrict__ enc) {
    int b = blockIdx.y;
    int h = blockIdx.x * 128 + threadIdx.x;
    __shared__ float sa[256];
    float acc = 0.f;
    for (int t0 = 0; t0 < T_; t0 += 256) {
        __syncthreads();
        for (int i = threadIdx.x; i < 256; i += 128) sa[i] = attn[b * T_ + t0 + i];
        __syncthreads();
        #pragma unroll 8
        for (int t = 0; t < 256; t++) acc += sa[t] * enc[(b * T_ + t0 + t) * H_ + h];
    }
    g_ctx[b * H_ + h] = acc;
}

// ---------------- LSTM gates: gates[b][j] = x.W_ih[j] + h.W_hh[j] + biases ----------------
__global__ void k_gates(const float* __restrict__ Wih, const float* __restrict__ Whh,
                        const float* __restrict__ bih, const float* __restrict__ bhh,
                        const float* __restrict__ hidden) {
    int j = blockIdx.x;  // 0..2047
    __shared__ float sw[1280];
    int tid = threadIdx.x;
    for (int i = tid; i < 768; i += 256) sw[i] = Wih[j * 768 + i];
    for (int i = tid; i < 512; i += 256) sw[768 + i] = Whh[j * 512 + i];
    __syncthreads();
    float bias = bih[j] + bhh[j];
    int w = tid >> 5, lane = tid & 31;
    for (int b = w; b < B_; b += 8) {
        float acc = 0.f;
        for (int k = lane; k < 256; k += 32) acc += sw[k] * g_embg[b * E_ + k];
        for (int k = lane; k < 512; k += 32)
            acc += sw[256 + k] * g_ctx[b * H_ + k] + sw[768 + k] * hidden[b * H_ + k];
        #pragma unroll
        for (int o = 16; o; o >>= 1) acc += __shfl_down_sync(0xffffffffu, acc, o);
        if (!lane) g_gates[b * G4H_ + j] = acc + bias;
    }
}

// ---------------- LSTM pointwise ----------------
__global__ void k_lstm(const float* __restrict__ cell,
                       float* __restrict__ hout, float* __restrict__ cout) {
    int b = blockIdx.x, h = threadIdx.x;  // 512 threads
    const float* g = g_gates + b * G4H_;
    float ig = sig_fast(g[h]);
    float fg = sig_fast(g[512 + h]);
    float gg = tanh_fast(g[1024 + h]);
    float og = sig_fast(g[1536 + h]);
    float cn = fg * cell[b * H_ + h] + ig * gg;
    float hn = og * tanh_fast(cn);
    cout[b * H_ + h] = cn;
    hout[b * H_ + h] = hn;
}

// ---------------- logits = [h_new || ctx] @ W_out^T + b_out ----------------
__global__ __launch_bounds__(256) void k_logits(
    const float* __restrict__ hnew, const float* __restrict__ Wout,
    const float* __restrict__ bout, float* __restrict__ out)
{
    __shared__ __align__(16) float A_s[64][68];  // [k][b]
    __shared__ __align__(16) float B_s[64][68];  // [k][v]
    int tid = threadIdx.x;
    int tx = tid & 15, ty = tid >> 4;
    int v0 = blockIdx.x * 64;

    float acc[4][4];
    #pragma unroll
    for (int i = 0; i < 4; i++)
        #pragma unroll
        for (int j = 0; j < 4; j++) acc[i][j] = 0.f;

    for (int k0 = 0; k0 < 1024; k0 += 64) {
        __syncthreads();
        #pragma unroll
        for (int idx = tid; idx < 4096; idx += 256) {
            int r = idx >> 6, k = idx & 63;
            int kk = k0 + k;
            A_s[k][r] = (kk < 512) ? hnew[r * H_ + kk] : g_ctx[r * H_ + kk - 512];
            int v = v0 + r;
            B_s[k][r] = (v < V_) ? Wout[v * 1024 + kk] : 0.f;
        }
        __syncthreads();
        #pragma unroll
        for (int k = 0; k < 64; k++) {
            float4 a = *(const float4*)(&A_s[k][ty * 4]);
            float4 w = *(const float4*)(&B_s[k][tx * 4]);
            acc[0][0] += a.x * w.x; acc[0][1] += a.x * w.y; acc[0][2] += a.x * w.z; acc[0][3] += a.x * w.w;
            acc[1][0] += a.y * w.x; acc[1][1] += a.y * w.y; acc[1][2] += a.y * w.z; acc[1][3] += a.y * w.w;
            acc[2][0] += a.z * w.x; acc[2][1] += a.z * w.y; acc[2][2] += a.z * w.z; acc[2][3] += a.z * w.w;
            acc[3][0] += a.w * w.x; acc[3][1] += a.w * w.y; acc[3][2] += a.w * w.z; acc[3][3] += a.w * w.w;
        }
    }
    #pragma unroll
    for (int i = 0; i < 4; i++) {
        int bb = ty * 4 + i;
        #pragma unroll
        for (int j = 0; j < 4; j++) {
            int v = v0 + tx * 4 + j;
            if (v < V_) out[bb * V_ + v] = acc[i][j] + bout[v];
        }
    }
}

// ---------------- host launcher ----------------
extern "C" void kernel_launch(void* const* d_in, const int* in_sizes, int n_in,
                              void* d_out, int out_size) {
    const int*   tok    = (const int*)  d_in[0];
    const float* hidden = (const float*)d_in[1];
    const float* cell   = (const float*)d_in[2];
    const float* enc    = (const float*)d_in[3];
    const float* emb    = (const float*)d_in[4];
    const float* Wenc   = (const float*)d_in[5];
    const float* Wdec   = (const float*)d_in[6];
    const float* vat    = (const float*)d_in[7];
    const float* Wih    = (const float*)d_in[8];
    const float* Whh    = (const float*)d_in[9];
    const float* bih    = (const float*)d_in[10];
    const float* bhh    = (const float*)d_in[11];
    const float* Wout   = (const float*)d_in[12];
    const float* bout   = (const float*)d_in[13];

    float* out        = (float*)d_out;
    float* out_logits = out;                              // (B,V)
    float* out_h      = out_logits + (size_t)B_ * V_;     // (1,B,H)
    float* out_c      = out_h + B_ * H_;                  // (1,B,H)
    float* out_attn   = out_c + B_ * H_;                  // (B,T)

    k_embed  <<<B_, E_>>>(tok, emb);
    k_dec    <<<B_, 256>>>(hidden, Wdec);
    k_energy <<<(B_ * T_) / 64, 256>>>(enc, Wenc, vat);
    k_softmax<<<B_, 256>>>(out_attn);
    k_context<<<dim3(4, B_), 128>>>(out_attn, enc);
    k_gates  <<<G4H_, 256>>>(Wih, Whh, bih, bhh, hidden);
    k_lstm   <<<B_, H_>>>(cell, out_h, out_c);
    k_logits <<<(V_ + 63) / 64, 256>>>(out_h, Wout, bout, out_logits);
}

// round 10
// speedup vs baseline: 3.5906x; 3.5906x over previous
#include <cuda_runtime.h>
#include <cstdint>

#define B_   64
#define T_   2048
#define H_   512
#define E_   256
#define V_   50000
#define G4H_ 2048

// ---------------- scratch (allocation-free: device globals) ----------------
__device__ float g_embg[B_ * E_];
__device__ float g_dec[B_ * H_];
__device__ float g_scores[B_ * T_];
__device__ float g_ctx[B_ * H_];
__device__ float g_ctxp[8 * B_ * H_];
__device__ float g_gates[B_ * G4H_];

// ---------------- helpers ----------------
__device__ __forceinline__ uint32_t smem_u32(const void* p) {
    uint32_t a;
    asm("{ .reg .u64 t; cvta.to.shared.u64 t, %1; cvt.u32.u64 %0, t; }" : "=r"(a) : "l"(p));
    return a;
}
__device__ __forceinline__ void cpa16(uint32_t s, const void* g) {
    asm volatile("cp.async.cg.shared.global [%0], [%1], 16;" :: "r"(s), "l"(g));
}
__device__ __forceinline__ void cpa_commit() {
    asm volatile("cp.async.commit_group;" ::: "memory");
}
__device__ __forceinline__ void cpa_wait1() {
    asm volatile("cp.async.wait_group 1;" ::: "memory");
}
__device__ __forceinline__ void cpa_wait0() {
    asm volatile("cp.async.wait_group 0;" ::: "memory");
}
__device__ __forceinline__ uint32_t ldtf32(const float* p) {
    uint32_t y; asm("cvt.rna.tf32.f32 %0, %1;" : "=r"(y) : "f"(*p));
    return y;
}
__device__ __forceinline__ void mma8(float* c, const uint32_t* a, uint32_t b0, uint32_t b1) {
    asm volatile(
        "mma.sync.aligned.m16n8k8.row.col.f32.tf32.tf32.f32 "
        "{%0,%1,%2,%3},{%4,%5,%6,%7},{%8,%9},{%0,%1,%2,%3};"
        : "+f"(c[0]), "+f"(c[1]), "+f"(c[2]), "+f"(c[3])
        : "r"(a[0]), "r"(a[1]), "r"(a[2]), "r"(a[3]), "r"(b0), "r"(b1));
}

// ---------------- transcendentals ----------------
__device__ __forceinline__ float tanh_fast(float x) {
    float e = __expf(2.f * x);
    return 1.f - __fdividef(2.f, e + 1.f);
}
__device__ __forceinline__ float sig_fast(float x) {
    return __fdividef(1.f, 1.f + __expf(-x));
}

extern __shared__ __align__(16) char dsm[];

// ================= k_energy_mma =================
// scores[b,t] = sum_h v[h] * tanh( [enc @ Wenc^T](t,h) + dec[b,h] )
// CTA: 128 rows (t), N-chunks of 128 (h) x4, K=512 in chunks of 32 (cp.async dbuf).
// Smem layout (bytes), row stride 36 floats:
#define ESTR  36
#define E_A0  0
#define E_A1  18432
#define E_B0  36864
#define E_B1  55296
#define E_DV  73728
#define E_VV  75776
#define E_SR  77824
#define E_SMEM 78848

__global__ void __launch_bounds__(256, 2) k_energy_mma(
    const float* __restrict__ enc, const float* __restrict__ Wenc,
    const float* __restrict__ vat)
{
    uint32_t sb = smem_u32(dsm);
    int tid = threadIdx.x, wid = tid >> 5, lane = tid & 31;
    int wm = wid & 3, wn = wid >> 2;       // 4 m-warps x 2 n-warps
    int q = lane >> 2, c4 = lane & 3;
    int m0 = blockIdx.x * 128;
    int b  = m0 >> 11;

    float* dv = (float*)(dsm + E_DV);
    float* vv = (float*)(dsm + E_VV);
    for (int i = tid; i < H_; i += 256) { dv[i] = g_dec[b * H_ + i]; vv[i] = vat[i]; }

    const uint32_t Ao[2] = {sb + E_A0, sb + E_A1};
    const uint32_t Bo[2] = {sb + E_B0, sb + E_B1};

    float sp[4] = {0.f, 0.f, 0.f, 0.f};
    __syncthreads();

    #pragma unroll 1
    for (int c0 = 0; c0 < H_; c0 += 128) {
        float acc[2][8][4];
        #pragma unroll
        for (int mi = 0; mi < 2; mi++)
            #pragma unroll
            for (int nj = 0; nj < 8; nj++)
                #pragma unroll
                for (int e = 0; e < 4; e++) acc[mi][nj][e] = 0.f;

        // preload chunk 0
        #pragma unroll
        for (int i = 0; i < 4; i++) {
            int idx = tid + i * 256, r = idx >> 3, c = idx & 7;
            cpa16(Ao[0] + (uint32_t)(r * ESTR + c * 4) * 4,
                  enc + (size_t)(m0 + r) * H_ + c * 4);
            cpa16(Bo[0] + (uint32_t)(r * ESTR + c * 4) * 4,
                  Wenc + (size_t)(c0 + r) * H_ + c * 4);
        }
        cpa_commit();

        #pragma unroll 1
        for (int s = 0; s < 16; s++) {
            if (s < 15) {
                int kc = (s + 1) * 32, nb = (s + 1) & 1;
                #pragma unroll
                for (int i = 0; i < 4; i++) {
                    int idx = tid + i * 256, r = idx >> 3, c = idx & 7;
                    cpa16(Ao[nb] + (uint32_t)(r * ESTR + c * 4) * 4,
                          enc + (size_t)(m0 + r) * H_ + kc + c * 4);
                    cpa16(Bo[nb] + (uint32_t)(r * ESTR + c * 4) * 4,
                          Wenc + (size_t)(c0 + r) * H_ + kc + c * 4);
                }
                cpa_commit();
                cpa_wait1();
            } else {
                cpa_wait0();
            }
            __syncthreads();

            const float* As = (const float*)(dsm + (((s & 1) ? E_A1 : E_A0)));
            const float* Bs = (const float*)(dsm + (((s & 1) ? E_B1 : E_B0)));
            #pragma unroll
            for (int k = 0; k < 32; k += 8) {
                uint32_t a[2][4];
                #pragma unroll
                for (int mi = 0; mi < 2; mi++) {
                    int r0 = wm * 32 + mi * 16 + q;
                    a[mi][0] = ldtf32(&As[r0 * ESTR + k + c4]);
                    a[mi][1] = ldtf32(&As[(r0 + 8) * ESTR + k + c4]);
                    a[mi][2] = ldtf32(&As[r0 * ESTR + k + c4 + 4]);
                    a[mi][3] = ldtf32(&As[(r0 + 8) * ESTR + k + c4 + 4]);
                }
                #pragma unroll
                for (int nj = 0; nj < 8; nj++) {
                    int nr = wn * 64 + nj * 8 + q;
                    uint32_t b0 = ldtf32(&Bs[nr * ESTR + k + c4]);
                    uint32_t b1 = ldtf32(&Bs[nr * ESTR + k + c4 + 4]);
                    mma8(acc[0][nj], a[0], b0, b1);
                    mma8(acc[1][nj], a[1], b0, b1);
                }
            }
            __syncthreads();
        }

        // fused epilogue for this N-chunk: tanh + v-weighted partial sums
        #pragma unroll
        for (int mi = 0; mi < 2; mi++) {
            #pragma unroll
            for (int nj = 0; nj < 8; nj++) {
                #pragma unroll
                for (int e = 0; e < 4; e++) {
                    int col = c0 + wn * 64 + nj * 8 + 2 * c4 + (e & 1);
                    float t = tanh_fast(acc[mi][nj][e] + dv[col]);
                    sp[mi * 2 + (e >> 1)] += t * vv[col];
                }
            }
        }
    }

    // reduce over the quad (4 lanes hold different columns)
    #pragma unroll
    for (int i = 0; i < 4; i++) {
        sp[i] += __shfl_xor_sync(0xffffffffu, sp[i], 1);
        sp[i] += __shfl_xor_sync(0xffffffffu, sp[i], 2);
    }
    float* sred = (float*)(dsm + E_SR);
    if (c4 == 0) {
        #pragma unroll
        for (int mi = 0; mi < 2; mi++)
            #pragma unroll
            for (int o8 = 0; o8 < 2; o8++) {
                int r = wm * 32 + mi * 16 + o8 * 8 + q;
                sred[wn * 128 + r] = sp[mi * 2 + o8];
            }
    }
    __syncthreads();
    if (tid < 128) g_scores[m0 + tid] = sred[tid] + sred[128 + tid];
}

// ================= k_logits_mma =================
// logits = [h_new || ctx](64x1024) @ W_out^T + b_out.  N-tile 128 of V, K=1024.
#define L_A0  0
#define L_A1  9216
#define L_B0  18432
#define L_B1  36864
#define L_SMEM 55296

__global__ void __launch_bounds__(256, 2) k_logits_mma(
    const float* __restrict__ hnew, const float* __restrict__ Wout,
    const float* __restrict__ bout, float* __restrict__ out)
{
    uint32_t sb = smem_u32(dsm);
    int tid = threadIdx.x, wid = tid >> 5, lane = tid & 31;
    int wm = wid & 1, wn = wid >> 1;       // 2 m-warps x 4 n-warps
    int q = lane >> 2, c4 = lane & 3;
    int v0 = blockIdx.x * 128;

    const uint32_t Ao[2] = {sb + L_A0, sb + L_A1};
    const uint32_t Bo[2] = {sb + L_B0, sb + L_B1};

    float acc[2][4][4];
    #pragma unroll
    for (int mi = 0; mi < 2; mi++)
        #pragma unroll
        for (int nj = 0; nj < 4; nj++)
            #pragma unroll
            for (int e = 0; e < 4; e++) acc[mi][nj][e] = 0.f;

    // chunk loader as a lambda-ish macro body
    #define L_LOAD(buf, kc) do {                                                   \
        const float* asrc = ((kc) < 512) ? (hnew + (kc)) : (g_ctx + (kc) - 512);   \
        {   int idx = tid, r = idx >> 3, c = idx & 7;                              \
            cpa16(Ao[buf] + (uint32_t)(r * ESTR + c * 4) * 4,                      \
                  asrc + (size_t)r * H_ + c * 4);                                  \
            idx = tid + 256; r = idx >> 3; c = idx & 7;                            \
            cpa16(Ao[buf] + (uint32_t)(r * ESTR + c * 4) * 4,                      \
                  asrc + (size_t)r * H_ + c * 4); }                                \
        _Pragma("unroll")                                                          \
        for (int i = 0; i < 4; i++) {                                              \
            int idx = tid + i * 256, r = idx >> 3, c = idx & 7;                    \
            int v = v0 + r;                                                        \
            uint32_t sa = Bo[buf] + (uint32_t)(r * ESTR + c * 4) * 4;              \
            if (v < V_) cpa16(sa, Wout + (size_t)v * 1024 + (kc) + c * 4);         \
            else { float4 z = make_float4(0.f,0.f,0.f,0.f);                        \
                   *(float4*)(dsm + (sa - sb)) = z; }                              \
        }                                                                          \
    } while (0)

    L_LOAD(0, 0);
    cpa_commit();

    #pragma unroll 1
    for (int s = 0; s < 32; s++) {
        if (s < 31) {
            int nb = (s + 1) & 1, kc = (s + 1) * 32;
            L_LOAD(nb, kc);
            cpa_commit();
            cpa_wait1();
        } else {
            cpa_wait0();
        }
        __syncthreads();

        const float* As = (const float*)(dsm + (((s & 1) ? L_A1 : L_A0)));
        const float* Bs = (const float*)(dsm + (((s & 1) ? L_B1 : L_B0)));
        #pragma unroll
        for (int k = 0; k < 32; k += 8) {
            uint32_t a[2][4];
            #pragma unroll
            for (int mi = 0; mi < 2; mi++) {
                int r0 = wm * 32 + mi * 16 + q;
                a[mi][0] = ldtf32(&As[r0 * ESTR + k + c4]);
                a[mi][1] = ldtf32(&As[(r0 + 8) * ESTR + k + c4]);
                a[mi][2] = ldtf32(&As[r0 * ESTR + k + c4 + 4]);
                a[mi][3] = ldtf32(&As[(r0 + 8) * ESTR + k + c4 + 4]);
            }
            #pragma unroll
            for (int nj = 0; nj < 4; nj++) {
                int nr = wn * 32 + nj * 8 + q;
                uint32_t b0 = ldtf32(&Bs[nr * ESTR + k + c4]);
                uint32_t b1 = ldtf32(&Bs[nr * ESTR + k + c4 + 4]);
                mma8(acc[0][nj], a[0], b0, b1);
                mma8(acc[1][nj], a[1], b0, b1);
            }
        }
        __syncthreads();
    }

    #pragma unroll
    for (int mi = 0; mi < 2; mi++) {
        #pragma unroll
        for (int nj = 0; nj < 4; nj++) {
            #pragma unroll
            for (int e = 0; e < 4; e++) {
                int row = wm * 32 + mi * 16 + ((e >> 1) ? q + 8 : q);
                int v = v0 + wn * 32 + nj * 8 + 2 * c4 + (e & 1);
                if (v < V_)
                    out[(size_t)row * V_ + v] = acc[mi][nj][e] + bout[v];
            }
        }
    }
    #undef L_LOAD
}

// ---------------- small kernels ----------------
__global__ void k_embed(const int* __restrict__ tok, const float* __restrict__ emb) {
    int b = blockIdx.x;
    g_embg[b * E_ + threadIdx.x] = emb[tok[b] * E_ + threadIdx.x];
}

__global__ void k_dec(const float* __restrict__ hidden, const float* __restrict__ Wdec) {
    int b = blockIdx.x;
    __shared__ float sh[H_];
    int tid = threadIdx.x;
    for (int i = tid; i < H_; i += 256) sh[i] = hidden[b * H_ + i];
    __syncthreads();
    int w = tid >> 5, lane = tid & 31;
    for (int h = w; h < H_; h += 8) {
        float acc = 0.f;
        for (int k = lane; k < H_; k += 32) acc += sh[k] * Wdec[h * H_ + k];
        #pragma unroll
        for (int o = 16; o; o >>= 1) acc += __shfl_down_sync(0xffffffffu, acc, o);
        if (!lane) g_dec[b * H_ + h] = acc;
    }
}

__global__ void k_softmax(float* __restrict__ attn) {
    int b = blockIdx.x;
    int tid = threadIdx.x;
    __shared__ float se[T_];
    __shared__ float rbuf[10];

    float m = -1e30f;
    for (int i = tid; i < T_; i += 256) { float v = g_scores[b * T_ + i]; se[i] = v; m = fmaxf(m, v); }
    #pragma unroll
    for (int o = 16; o; o >>= 1) m = fmaxf(m, __shfl_xor_sync(0xffffffffu, m, o));
    if ((tid & 31) == 0) rbuf[tid >> 5] = m;
    __syncthreads();
    if (tid == 0) { float v = rbuf[0]; for (int i = 1; i < 8; i++) v = fmaxf(v, rbuf[i]); rbuf[8] = v; }
    __syncthreads();
    m = rbuf[8];

    float s = 0.f;
    for (int i = tid; i < T_; i += 256) { float e = __expf(se[i] - m); se[i] = e; s += e; }
    #pragma unroll
    for (int o = 16; o; o >>= 1) s += __shfl_xor_sync(0xffffffffu, s, o);
    if ((tid & 31) == 0) rbuf[tid >> 5] = s;
    __syncthreads();
    if (tid == 0) { float v = 0.f; for (int i = 0; i < 8; i++) v += rbuf[i]; rbuf[9] = v; }
    __syncthreads();
    float inv = __fdividef(1.f, rbuf[9]);
    for (int i = tid; i < T_; i += 256) attn[b * T_ + i] = se[i] * inv;
}

__global__ void k_context(const float* __restrict__ attn, const float* __restrict__ enc) {
    int sl = blockIdx.x, b = blockIdx.y;
    int tid = threadIdx.x;  // 128
    __shared__ float sa[256];
    int t0 = sl * 256;
    for (int i = tid; i < 256; i += 128) sa[i] = attn[b * T_ + t0 + i];
    __syncthreads();
    float4 acc = make_float4(0.f, 0.f, 0.f, 0.f);
    #pragma unroll 4
    for (int t = 0; t < 256; t++) {
        float a = sa[t];
        float4 e = *(const float4*)(enc + ((size_t)(b * T_ + t0 + t)) * H_ + tid * 4);
        acc.x += a * e.x; acc.y += a * e.y; acc.z += a * e.z; acc.w += a * e.w;
    }
    *(float4*)(&g_ctxp[(size_t)(sl * B_ + b) * H_ + tid * 4]) = acc;
}

__global__ void k_ctxred() {
    int i = blockIdx.x * 256 + threadIdx.x;
    float s = 0.f;
    #pragma unroll
    for (int sl = 0; sl < 8; sl++) s += g_ctxp[sl * B_ * H_ + i];
    g_ctx[i] = s;
}

__global__ void k_gates(const float* __restrict__ Wih, const float* __restrict__ Whh,
                        const float* __restrict__ bih, const float* __restrict__ bhh,
                        const float* __restrict__ hidden) {
    int j = blockIdx.x;
    __shared__ float sw[1280];
    int tid = threadIdx.x;
    for (int i = tid; i < 768; i += 256) sw[i] = Wih[j * 768 + i];
    for (int i = tid; i < 512; i += 256) sw[768 + i] = Whh[j * 512 + i];
    __syncthreads();
    float bias = bih[j] + bhh[j];
    int w = tid >> 5, lane = tid & 31;
    for (int b = w; b < B_; b += 8) {
        float acc = 0.f;
        for (int k = lane; k < 256; k += 32) acc += sw[k] * g_embg[b * E_ + k];
        for (int k = lane; k < 512; k += 32)
            acc += sw[256 + k] * g_ctx[b * H_ + k] + sw[768 + k] * hidden[b * H_ + k];
        #pragma unroll
        for (int o = 16; o; o >>= 1) acc += __shfl_down_sync(0xffffffffu, acc, o);
        if (!lane) g_gates[b * G4H_ + j] = acc + bias;
    }
}

__global__ void k_lstm(const float* __restrict__ cell,
                       float* __restrict__ hout, float* __restrict__ cout) {
    int b = blockIdx.x, h = threadIdx.x;
    const float* g = g_gates + b * G4H_;
    float ig = sig_fast(g[h]);
    float fg = sig_fast(g[512 + h]);
    float gg = tanh_fast(g[1024 + h]);
    float og = sig_fast(g[1536 + h]);
    float cn = fg * cell[b * H_ + h] + ig * gg;
    float hn = og * tanh_fast(cn);
    cout[b * H_ + h] = cn;
    hout[b * H_ + h] = hn;
}

// ---------------- host launcher ----------------
extern "C" void kernel_launch(void* const* d_in, const int* in_sizes, int n_in,
                              void* d_out, int out_size) {
    const int*   tok    = (const int*)  d_in[0];
    const float* hidden = (const float*)d_in[1];
    const float* cell   = (const float*)d_in[2];
    const float* enc    = (const float*)d_in[3];
    const float* emb    = (const float*)d_in[4];
    const float* Wenc   = (const float*)d_in[5];
    const float* Wdec   = (const float*)d_in[6];
    const float* vat    = (const float*)d_in[7];
    const float* Wih    = (const float*)d_in[8];
    const float* Whh    = (const float*)d_in[9];
    const float* bih    = (const float*)d_in[10];
    const float* bhh    = (const float*)d_in[11];
    const float* Wout   = (const float*)d_in[12];
    const float* bout   = (const float*)d_in[13];

    float* out        = (float*)d_out;
    float* out_logits = out;
    float* out_h      = out_logits + (size_t)B_ * V_;
    float* out_c      = out_h + B_ * H_;
    float* out_attn   = out_c + B_ * H_;

    cudaFuncSetAttribute(k_energy_mma, cudaFuncAttributeMaxDynamicSharedMemorySize, E_SMEM);
    cudaFuncSetAttribute(k_logits_mma, cudaFuncAttributeMaxDynamicSharedMemorySize, L_SMEM);

    k_embed     <<<B_, E_>>>(tok, emb);
    k_dec       <<<B_, 256>>>(hidden, Wdec);
    k_energy_mma<<<(B_ * T_) / 128, 256, E_SMEM>>>(enc, Wenc, vat);
    k_softmax   <<<B_, 256>>>(out_attn);
    k_context   <<<dim3(8, B_), 128>>>(out_attn, enc);
    k_ctxred    <<<(B_ * H_) / 256, 256>>>();
    k_gates     <<<G4H_, 256>>>(Wih, Whh, bih, bhh, hidden);
    k_lstm      <<<B_, H_>>>(cell, out_h, out_c);
    k_logits_mma<<<(V_ + 127) / 128, 256, L_SMEM>>>(out_h, Wout, bout, out_logits);
}